// round 1
// baseline (speedup 1.0000x reference)
#include <cuda_runtime.h>

// Problem constants
#define B_  4
#define F_  5
#define P_  920
#define N_  4600          // F_*P_
#define C_  512
#define H_  8
#define DH_ 64
#define M_  (B_*N_)       // 18400
#define MKV_ (M_*F_)      // 92000
#define OUT1_ 9420800     // 920*20*512 (first tuple output element count)

// ---------------- scratch (static device globals; no allocations) -----------
static __device__ float g_x[(size_t)M_ * C_];                 // xb (B*N, C)
static __device__ float g_qkv[(size_t)M_ * 3 * C_];           // q|k|v  (B*N, 1536)
static __device__ float g_scores[(size_t)B_ * N_ * N_];       // (B, N, N) -> attn1 in place
static __device__ float g_xo[(size_t)M_ * F_ * C_];           // (B*N, F, C)
static __device__ float g_xdiag[(size_t)M_ * C_];
static __device__ float g_q2[(size_t)M_ * C_];
static __device__ float g_k2v2[(size_t)MKV_ * 2 * C_];        // (B*N*F, k2|v2)
static __device__ float g_out2[(size_t)M_ * C_];
static __device__ float g_out2p[(size_t)M_ * C_];

// ---------------- generic tiled fp32 GEMM  C = alpha * A x B ----------------
// 64x64 block tile, BK=16, 4x4 per thread, 256 threads.
// Batched via blockIdx.z with two-level (zb, zf) offset decomposition.
template<bool TRANSB>
__global__ void gemm_tiled(const float* __restrict__ A,
                           const float* __restrict__ B,
                           float* __restrict__ C,
                           int M, int N, int K,
                           int lda, int ldb, int ldc,
                           int Z2,
                           long sA1, long sA2, long sB1, long sB2,
                           long sC1, long sC2,
                           float alpha)
{
    __shared__ float As[16][68];
    __shared__ float Bs[16][68];

    int z  = blockIdx.z;
    int zb = z / Z2, zf = z % Z2;
    A += (long)zb * sA1 + (long)zf * sA2;
    B += (long)zb * sB1 + (long)zf * sB2;
    C += (long)zb * sC1 + (long)zf * sC2;

    int bm = blockIdx.y * 64;
    int bn = blockIdx.x * 64;
    int tid = threadIdx.x;
    int tm = (tid >> 4) << 2;   // 0..60
    int tn = (tid & 15) << 2;   // 0..60

    float acc[4][4];
#pragma unroll
    for (int i = 0; i < 4; i++)
#pragma unroll
        for (int j = 0; j < 4; j++) acc[i][j] = 0.f;

    for (int k0 = 0; k0 < K; k0 += 16) {
        // Load A tile (64 rows x 16 k), coalesced along k
#pragma unroll
        for (int i = 0; i < 4; i++) {
            int e = i * 256 + tid;
            int m = e >> 4, k = e & 15;
            int gm = bm + m, gk = k0 + k;
            float v = 0.f;
            if (gm < M && gk < K) v = A[(long)gm * lda + gk];
            As[k][m] = v;
        }
        // Load B tile (16 k x 64 n)
#pragma unroll
        for (int i = 0; i < 4; i++) {
            int e = i * 256 + tid;
            float v = 0.f;
            if (!TRANSB) {
                int k = e >> 6, n = e & 63;
                int gk = k0 + k, gn = bn + n;
                if (gk < K && gn < N) v = B[(long)gk * ldb + gn];
                Bs[k][n] = v;
            } else {
                int n = e >> 4, k = e & 15;
                int gn = bn + n, gk = k0 + k;
                if (gn < N && gk < K) v = B[(long)gn * ldb + gk];
                Bs[k][n] = v;
            }
        }
        __syncthreads();

#pragma unroll
        for (int kk = 0; kk < 16; kk++) {
            float ar[4], br[4];
#pragma unroll
            for (int i = 0; i < 4; i++) ar[i] = As[kk][tm + i];
#pragma unroll
            for (int j = 0; j < 4; j++) br[j] = Bs[kk][tn + j];
#pragma unroll
            for (int i = 0; i < 4; i++)
#pragma unroll
                for (int j = 0; j < 4; j++)
                    acc[i][j] += ar[i] * br[j];
        }
        __syncthreads();
    }

#pragma unroll
    for (int i = 0; i < 4; i++) {
        int gm = bm + tm + i;
        if (gm >= M) continue;
#pragma unroll
        for (int j = 0; j < 4; j++) {
            int gn = bn + tn + j;
            if (gn < N) C[(long)gm * ldc + gn] = alpha * acc[i][j];
        }
    }
}

// ---------------- small kernels ----------------------------------------------
// x (S=4600, B0=4, C) -> g_x (B*N, C)
__global__ void transpose_x(const float* __restrict__ x, float* __restrict__ gx)
{
    long idx = (long)blockIdx.x * 256 + threadIdx.x;
    if (idx >= (long)M_ * C_) return;
    int c = (int)(idx & (C_ - 1));
    long m = idx >> 9;            // /512
    int b = (int)(m / N_);
    int n = (int)(m % N_);
    gx[idx] = x[((long)n * B_ + b) * C_ + c];
}

// softmax over P within each (b, q, f) row of scores, with scale=dh^-0.5
__global__ void softmax_frames(float* __restrict__ sc)
{
    int rid = blockIdx.x;               // (b*N+q)*F + f
    long bq = rid / F_;
    int  f  = rid % F_;
    float* row = sc + bq * (long)N_ + (long)f * P_;
    int t = threadIdx.x;                 // 128 threads

    float v[8];
    float mx = -1e30f;
#pragma unroll
    for (int i = 0; i < 8; i++) {
        int p = t + i * 128;
        if (p < P_) { float x = row[p] * 0.125f; v[i] = x; mx = fmaxf(mx, x); }
        else v[i] = -1e30f;
    }
    __shared__ float red[128];
    red[t] = mx; __syncthreads();
    for (int s = 64; s > 0; s >>= 1) {
        if (t < s) red[t] = fmaxf(red[t], red[t + s]);
        __syncthreads();
    }
    mx = red[0];
    __syncthreads();

    float sum = 0.f;
#pragma unroll
    for (int i = 0; i < 8; i++) {
        int p = t + i * 128;
        if (p < P_) { float e = expf(v[i] - mx); v[i] = e; sum += e; }
    }
    red[t] = sum; __syncthreads();
    for (int s = 64; s > 0; s >>= 1) {
        if (t < s) red[t] += red[t + s];
        __syncthreads();
    }
    float inv = 1.f / red[0];
#pragma unroll
    for (int i = 0; i < 8; i++) {
        int p = t + i * 128;
        if (p < P_) row[p] = v[i] * inv;
    }
}

// x_diag[m, c] = xo[m, f = (m % N)/P, c]
__global__ void diag_gather(const float* __restrict__ xo, float* __restrict__ xd)
{
    long idx = (long)blockIdx.x * 256 + threadIdx.x;
    if (idx >= (long)M_ * C_) return;
    int c = (int)(idx & (C_ - 1));
    long m = idx >> 9;
    int s = (int)(m % N_);
    int f = s / P_;
    xd[idx] = xo[((long)m * F_ + f) * C_ + c];
}

// Stage-2 temporal attention: one block per (b*N+s), one warp per head.
__global__ void stage2_attn(const float* __restrict__ q2,
                            const float* __restrict__ kv,
                            float* __restrict__ out2,
                            float* __restrict__ attn2)
{
    int m = blockIdx.x;                  // b*N + s
    int b = m / N_, s = m % N_;
    int w = threadIdx.x >> 5;            // head
    int l = threadIdx.x & 31;

    const float* qv = q2 + (long)m * C_ + w * DH_;
    float q0 = qv[l], q1 = qv[l + 32];

    float wgt[F_];
    float mx = -1e30f;
#pragma unroll
    for (int f = 0; f < F_; f++) {
        const float* kf = kv + ((long)m * F_ + f) * (2 * C_) + w * DH_;
        float p = q0 * kf[l] + q1 * kf[l + 32];
#pragma unroll
        for (int o = 16; o > 0; o >>= 1) p += __shfl_xor_sync(0xffffffffu, p, o);
        wgt[f] = p;
        mx = fmaxf(mx, p);
    }
    float sum = 0.f;
#pragma unroll
    for (int f = 0; f < F_; f++) { wgt[f] = expf(wgt[f] - mx); sum += wgt[f]; }
    float inv = 1.f / sum;
#pragma unroll
    for (int f = 0; f < F_; f++) wgt[f] *= inv;

    if (l < F_)
        attn2[(((long)b * H_ + w) * N_ + s) * F_ + l] = wgt[l];

    float o0 = 0.f, o1 = 0.f;
#pragma unroll
    for (int f = 0; f < F_; f++) {
        const float* vf = kv + ((long)m * F_ + f) * (2 * C_) + C_ + w * DH_;
        o0 += wgt[f] * vf[l];
        o1 += wgt[f] * vf[l + 32];
    }
    out2[(long)m * C_ + w * DH_ + l]      = o0;
    out2[(long)m * C_ + w * DH_ + l + 32] = o1;
}

// Final: add bias and permute (B,F,P,C) -> (P, B*F, C)
__global__ void scatter_out(const float* __restrict__ o,
                            const float* __restrict__ bias,
                            float* __restrict__ out)
{
    long idx = (long)blockIdx.x * 256 + threadIdx.x;
    if (idx >= (long)M_ * C_) return;
    int c = (int)(idx & (C_ - 1));
    long m = idx >> 9;
    int b = (int)(m / N_);
    int s = (int)(m % N_);
    int f = s / P_;
    int p = s % P_;
    out[(long)p * (B_ * F_ * C_) + ((long)b * F_ + f) * C_ + c] = o[idx] + bias[c];
}

// ---------------- host launcher ----------------------------------------------
static void launch_gemm(const float* A, const float* B, float* C,
                        int M, int N, int K, int lda, int ldb, int ldc,
                        int Z, int Z2,
                        long sA1, long sA2, long sB1, long sB2,
                        long sC1, long sC2, float alpha, bool transb)
{
    dim3 grid((N + 63) / 64, (M + 63) / 64, Z);
    if (transb)
        gemm_tiled<true><<<grid, 256>>>(A, B, C, M, N, K, lda, ldb, ldc,
                                        Z2, sA1, sA2, sB1, sB2, sC1, sC2, alpha);
    else
        gemm_tiled<false><<<grid, 256>>>(A, B, C, M, N, K, lda, ldb, ldc,
                                         Z2, sA1, sA2, sB1, sB2, sC1, sC2, alpha);
}

extern "C" void kernel_launch(void* const* d_in, const int* in_sizes, int n_in,
                              void* d_out, int out_size)
{
    (void)in_sizes; (void)n_in; (void)out_size;
    const float* x      = (const float*)d_in[0];
    const float* W_qkv  = (const float*)d_in[1];
    const float* W_q2   = (const float*)d_in[2];
    const float* W_kv2  = (const float*)d_in[3];
    const float* W_proj = (const float*)d_in[4];
    const float* b_proj = (const float*)d_in[5];
    float* out = (float*)d_out;

    float *px, *pqkv, *pscores, *pxo, *pxd, *pq2, *pkv, *po2, *po2p;
    cudaGetSymbolAddress((void**)&px,      g_x);
    cudaGetSymbolAddress((void**)&pqkv,    g_qkv);
    cudaGetSymbolAddress((void**)&pscores, g_scores);
    cudaGetSymbolAddress((void**)&pxo,     g_xo);
    cudaGetSymbolAddress((void**)&pxd,     g_xdiag);
    cudaGetSymbolAddress((void**)&pq2,     g_q2);
    cudaGetSymbolAddress((void**)&pkv,     g_k2v2);
    cudaGetSymbolAddress((void**)&po2,     g_out2);
    cudaGetSymbolAddress((void**)&po2p,    g_out2p);

    const long elems = (long)M_ * C_;
    const int  eb    = (int)((elems + 255) / 256);

    // 1) xb = transpose(x)
    transpose_x<<<eb, 256>>>(x, px);

    // 2) qkv = xb @ W_qkv   (18400 x 1536 x 512)
    launch_gemm(px, W_qkv, pqkv, M_, 3 * C_, C_, C_, 3 * C_, 3 * C_,
                1, 1, 0, 0, 0, 0, 0, 0, 1.0f, false);

    // 3) scores[b] = Q_b @ K_b^T   (4 batches of 4600 x 4600 x 512)
    launch_gemm(pqkv, pqkv + C_, pscores, N_, N_, C_, 3 * C_, 3 * C_, N_,
                B_, 1,
                (long)N_ * 3 * C_, 0, (long)N_ * 3 * C_, 0,
                (long)N_ * N_, 0, 1.0f, true);

    // 4) softmax(scale * scores) over P within each frame, in place
    softmax_frames<<<M_ * F_, 128>>>(pscores);

    // 5) xo[b,:,f,:] = attn1[b,:,f,:] @ V[b,f]   (20 batches of 4600 x 512 x 920)
    launch_gemm(pscores, pqkv + 2 * C_, pxo, N_, C_, P_, N_, 3 * C_, F_ * C_,
                B_ * F_, F_,
                (long)N_ * N_, (long)P_,
                (long)N_ * 3 * C_, (long)P_ * 3 * C_,
                (long)N_ * F_ * C_, (long)C_, 1.0f, false);

    // 6) diagonal gather
    diag_gather<<<eb, 256>>>(pxo, pxd);

    // 7) q2 = (x_diag @ W_q2) * scale
    launch_gemm(pxd, W_q2, pq2, M_, C_, C_, C_, C_, C_,
                1, 1, 0, 0, 0, 0, 0, 0, 0.125f, false);

    // 8) k2|v2 = xo @ W_kv2   (92000 x 1024 x 512)
    launch_gemm(pxo, W_kv2, pkv, MKV_, 2 * C_, C_, C_, 2 * C_, 2 * C_,
                1, 1, 0, 0, 0, 0, 0, 0, 1.0f, false);

    // 9) temporal attention; attn2 written straight into d_out tail
    stage2_attn<<<M_, 256>>>(pq2, pkv, po2, out + OUT1_);

    // 10) proj
    launch_gemm(po2, W_proj, po2p, M_, C_, C_, C_, C_, C_,
                1, 1, 0, 0, 0, 0, 0, 0, 1.0f, false);

    // 11) bias + output permutation
    scatter_out<<<eb, 256>>>(po2p, b_proj, out);
}

// round 3
// speedup vs baseline: 1.3768x; 1.3768x over previous
#include <cuda_runtime.h>
#include <cuda_bf16.h>

// Problem constants
#define B_  4
#define F_  5
#define P_  920
#define N_  4600          // F_*P_
#define C_  512
#define H_  8
#define DH_ 64
#define M_  (B_*N_)       // 18400
#define MKV_ (M_*F_)      // 92000
#define OUT1_ 9420800     // 920*20*512 (first tuple output element count)

// ---------------- scratch (static device globals; no allocations) -----------
static __device__ float g_x[(size_t)M_ * C_];                 // xb (B*N, C)
static __device__ float g_qkv[(size_t)M_ * 3 * C_];           // q|k|v  (B*N, 1536)
static __device__ float g_scores[(size_t)B_ * N_ * N_];       // (B, N, N) -> attn1 in place
static __device__ float g_xo[(size_t)M_ * F_ * C_];           // (B*N, F, C)
static __device__ float g_xdiag[(size_t)M_ * C_];
static __device__ float g_q2[(size_t)M_ * C_];
static __device__ float g_k2v2[(size_t)MKV_ * 2 * C_];        // (B*N*F, k2|v2)
static __device__ float g_out2[(size_t)M_ * C_];
static __device__ float g_out2p[(size_t)M_ * C_];

// ---------------- bf16 split helpers -----------------------------------------
__device__ __forceinline__ unsigned pack_bf2(__nv_bfloat16 a, __nv_bfloat16 b) {
    __nv_bfloat162 t; t.x = a; t.y = b;
    return *reinterpret_cast<unsigned*>(&t);
}

// split a float2 (two consecutive k) into {hi0,hi1} and {lo0,lo1} packets
__device__ __forceinline__ uint2 split2(float2 v) {
    __nv_bfloat16 h0 = __float2bfloat16_rn(v.x);
    __nv_bfloat16 h1 = __float2bfloat16_rn(v.y);
    __nv_bfloat16 l0 = __float2bfloat16_rn(v.x - __bfloat162float(h0));
    __nv_bfloat16 l1 = __float2bfloat16_rn(v.y - __bfloat162float(h1));
    uint2 e;
    e.x = pack_bf2(h0, h1);
    e.y = pack_bf2(l0, l1);
    return e;
}

__device__ __forceinline__ void mma_bf16(float* c, const unsigned* a, const unsigned* b) {
    asm volatile(
        "mma.sync.aligned.m16n8k16.row.col.f32.bf16.bf16.f32 "
        "{%0,%1,%2,%3}, {%4,%5,%6,%7}, {%8,%9}, {%0,%1,%2,%3};"
        : "+f"(c[0]), "+f"(c[1]), "+f"(c[2]), "+f"(c[3])
        : "r"(a[0]), "r"(a[1]), "r"(a[2]), "r"(a[3]),
          "r"(b[0]), "r"(b[1]));
}

// ---------------- bf16x3 tensor-core GEMM  C = alpha * A x B(^T) -------------
// 128x128 block tile, BK=32, 8 warps (2m x 4n), warp tile 64x32.
// Each smem entry (8B) = {hi(k),hi(k+1),lo(k),lo(k+1)} -> one LDS.64 per frag pair.
// Double-buffered via register staging. fp32 accuracy: C += Al*Bh + Ah*Bl + Ah*Bh.
#define BM 128
#define BN 128
#define BK 32
#define KPT   16          // k-pair entries per row
#define ROWE  17          // row stride in uint2 (KPT + 1 pad)
#define TILE_E (128 * ROWE)       // 2176 uint2 per tile
#define SMEM_BYTES (2 * 2 * TILE_E * 8)   // 69632

template<bool TRANSB>
__global__ __launch_bounds__(256)
void gemm_bf16x3(const float* __restrict__ A,
                 const float* __restrict__ B,
                 float* __restrict__ C,
                 int M, int N, int K,
                 int lda, int ldb, int ldc,
                 int Z2,
                 long sA1, long sA2, long sB1, long sB2,
                 long sC1, long sC2,
                 float alpha)
{
    extern __shared__ __align__(16) unsigned char dsm[];
    uint2* sbase = reinterpret_cast<uint2*>(dsm);
    // layout: [buf0: As | Bs][buf1: As | Bs]

    int z  = blockIdx.z;
    int zb = z / Z2, zf = z % Z2;
    A += (long)zb * sA1 + (long)zf * sA2;
    B += (long)zb * sB1 + (long)zf * sB2;
    C += (long)zb * sC1 + (long)zf * sC2;

    const int bm = blockIdx.y * BM;
    const int bn = blockIdx.x * BN;
    const int tid  = threadIdx.x;
    const int lane = tid & 31;
    const int gid  = lane >> 2;
    const int tig  = lane & 3;
    const int wid  = tid >> 5;
    const int wm   = wid >> 2;     // 0..1
    const int wn   = wid & 3;      // 0..3

    float acc[4][4][4];
#pragma unroll
    for (int i = 0; i < 4; i++)
#pragma unroll
        for (int j = 0; j < 4; j++)
#pragma unroll
            for (int t = 0; t < 4; t++) acc[i][j][t] = 0.f;

    const int kt = (K + BK - 1) / BK;

    // indices for tile loads
    const int la_m  = tid >> 4;      // + p*16
    const int la_kp = tid & 15;
    const int lb_k  = tid >> 7;      // + p*2 (non-trans path)
    const int lb_n  = tid & 127;

    // ---- prologue: tile 0 into buffer 0 ----
    {
        uint2* As = sbase;
        uint2* Bs = sbase + TILE_E;
#pragma unroll
        for (int p = 0; p < 8; p++) {
            int m = la_m + p * 16;
            int gm = bm + m, gk = 2 * la_kp;
            float2 v = make_float2(0.f, 0.f);
            if (gm < M && gk < K) v = *reinterpret_cast<const float2*>(&A[(long)gm * lda + gk]);
            As[m * ROWE + la_kp] = split2(v);
        }
        if (TRANSB) {
#pragma unroll
            for (int p = 0; p < 8; p++) {
                int n = la_m + p * 16;
                int gn = bn + n, gk = 2 * la_kp;
                float2 v = make_float2(0.f, 0.f);
                if (gn < N && gk < K) v = *reinterpret_cast<const float2*>(&B[(long)gn * ldb + gk]);
                Bs[n * ROWE + la_kp] = split2(v);
            }
        } else {
#pragma unroll
            for (int p = 0; p < 16; p++) {
                int k = lb_k + p * 2;
                int gk = k, gn = bn + lb_n;
                float v = 0.f;
                if (gk < K && gn < N) v = B[(long)gk * ldb + gn];
                __nv_bfloat16 h = __float2bfloat16_rn(v);
                __nv_bfloat16 l = __float2bfloat16_rn(v - __bfloat162float(h));
                unsigned short* ps =
                    reinterpret_cast<unsigned short*>(&Bs[lb_n * ROWE + (k >> 1)]);
                ps[k & 1]       = *reinterpret_cast<unsigned short*>(&h);
                ps[2 + (k & 1)] = *reinterpret_cast<unsigned short*>(&l);
            }
        }
    }
    __syncthreads();

    const int r0 = wm * 64 + gid;
    const int c0 = wn * 32 + gid;

    float2 ra[8];
    float2 rbt[8];     // TRANSB staging
    float  rbs[16];    // non-trans staging

    for (int it = 0; it < kt; it++) {
        const int cur  = it & 1;
        const int k0   = (it + 1) * BK;
        const bool more = (it + 1 < kt);

        // ---- stage next tile into registers ----
        if (more) {
#pragma unroll
            for (int p = 0; p < 8; p++) {
                int m = la_m + p * 16;
                int gm = bm + m, gk = k0 + 2 * la_kp;
                float2 v = make_float2(0.f, 0.f);
                if (gm < M && gk < K) v = *reinterpret_cast<const float2*>(&A[(long)gm * lda + gk]);
                ra[p] = v;
            }
            if (TRANSB) {
#pragma unroll
                for (int p = 0; p < 8; p++) {
                    int n = la_m + p * 16;
                    int gn = bn + n, gk = k0 + 2 * la_kp;
                    float2 v = make_float2(0.f, 0.f);
                    if (gn < N && gk < K) v = *reinterpret_cast<const float2*>(&B[(long)gn * ldb + gk]);
                    rbt[p] = v;
                }
            } else {
#pragma unroll
                for (int p = 0; p < 16; p++) {
                    int gk = k0 + lb_k + p * 2;
                    int gn = bn + lb_n;
                    float v = 0.f;
                    if (gk < K && gn < N) v = B[(long)gk * ldb + gn];
                    rbs[p] = v;
                }
            }
        }

        // ---- compute on current buffer ----
        const uint2* As = sbase + cur * 2 * TILE_E;
        const uint2* Bs = As + TILE_E;
#pragma unroll
        for (int ks = 0; ks < 2; ks++) {
            const int kpb = ks * 8;
            unsigned ah[4][4], al[4][4], bh[4][2], bl[4][2];
#pragma unroll
            for (int mt = 0; mt < 4; mt++) {
                int r = r0 + mt * 16;
                uint2 e00 = As[(r)     * ROWE + kpb + tig];
                uint2 e10 = As[(r + 8) * ROWE + kpb + tig];
                uint2 e01 = As[(r)     * ROWE + kpb + tig + 4];
                uint2 e11 = As[(r + 8) * ROWE + kpb + tig + 4];
                ah[mt][0] = e00.x; ah[mt][1] = e10.x; ah[mt][2] = e01.x; ah[mt][3] = e11.x;
                al[mt][0] = e00.y; al[mt][1] = e10.y; al[mt][2] = e01.y; al[mt][3] = e11.y;
            }
#pragma unroll
            for (int nt = 0; nt < 4; nt++) {
                int c = c0 + nt * 8;
                uint2 f0 = Bs[c * ROWE + kpb + tig];
                uint2 f1 = Bs[c * ROWE + kpb + tig + 4];
                bh[nt][0] = f0.x; bh[nt][1] = f1.x;
                bl[nt][0] = f0.y; bl[nt][1] = f1.y;
            }
#pragma unroll
            for (int mt = 0; mt < 4; mt++)
#pragma unroll
                for (int nt = 0; nt < 4; nt++) {
                    mma_bf16(acc[mt][nt], al[mt], bh[nt]);
                    mma_bf16(acc[mt][nt], ah[mt], bl[nt]);
                    mma_bf16(acc[mt][nt], ah[mt], bh[nt]);
                }
        }

        // ---- store staged regs into the other buffer ----
        if (more) {
            uint2* Asn = sbase + (cur ^ 1) * 2 * TILE_E;
            uint2* Bsn = Asn + TILE_E;
#pragma unroll
            for (int p = 0; p < 8; p++) {
                int m = la_m + p * 16;
                Asn[m * ROWE + la_kp] = split2(ra[p]);
            }
            if (TRANSB) {
#pragma unroll
                for (int p = 0; p < 8; p++) {
                    int n = la_m + p * 16;
                    Bsn[n * ROWE + la_kp] = split2(rbt[p]);
                }
            } else {
#pragma unroll
                for (int p = 0; p < 16; p++) {
                    int k = lb_k + p * 2;
                    float v = rbs[p];
                    __nv_bfloat16 h = __float2bfloat16_rn(v);
                    __nv_bfloat16 l = __float2bfloat16_rn(v - __bfloat162float(h));
                    unsigned short* ps =
                        reinterpret_cast<unsigned short*>(&Bsn[lb_n * ROWE + (k >> 1)]);
                    ps[k & 1]       = *reinterpret_cast<unsigned short*>(&h);
                    ps[2 + (k & 1)] = *reinterpret_cast<unsigned short*>(&l);
                }
            }
        }
        __syncthreads();
    }

    // ---- epilogue ----
#pragma unroll
    for (int mt = 0; mt < 4; mt++) {
#pragma unroll
        for (int nt = 0; nt < 4; nt++) {
            int row = bm + wm * 64 + mt * 16 + gid;
            int col = bn + wn * 32 + nt * 8 + tig * 2;
            if (row < M) {
                if (col < N)     C[(long)row * ldc + col]     = alpha * acc[mt][nt][0];
                if (col + 1 < N) C[(long)row * ldc + col + 1] = alpha * acc[mt][nt][1];
            }
            if (row + 8 < M) {
                if (col < N)     C[(long)(row + 8) * ldc + col]     = alpha * acc[mt][nt][2];
                if (col + 1 < N) C[(long)(row + 8) * ldc + col + 1] = alpha * acc[mt][nt][3];
            }
        }
    }
}

// ---------------- small kernels ----------------------------------------------
__global__ void transpose_x(const float* __restrict__ x, float* __restrict__ gx)
{
    long idx = (long)blockIdx.x * 256 + threadIdx.x;
    if (idx >= (long)M_ * C_) return;
    int c = (int)(idx & (C_ - 1));
    long m = idx >> 9;
    int b = (int)(m / N_);
    int n = (int)(m % N_);
    gx[idx] = x[((long)n * B_ + b) * C_ + c];
}

// softmax over P within each (b, q, f) row (scale folded into scores GEMM)
__global__ void softmax_frames(float* __restrict__ sc)
{
    int rid = blockIdx.x;
    long bq = rid / F_;
    int  f  = rid % F_;
    float* row = sc + bq * (long)N_ + (long)f * P_;
    int t = threadIdx.x;

    float v[8];
    float mx = -1e30f;
#pragma unroll
    for (int i = 0; i < 8; i++) {
        int p = t + i * 128;
        if (p < P_) { float x = row[p]; v[i] = x; mx = fmaxf(mx, x); }
        else v[i] = -1e30f;
    }
    __shared__ float red[128];
    red[t] = mx; __syncthreads();
    for (int s = 64; s > 0; s >>= 1) {
        if (t < s) red[t] = fmaxf(red[t], red[t + s]);
        __syncthreads();
    }
    mx = red[0];
    __syncthreads();

    float sum = 0.f;
#pragma unroll
    for (int i = 0; i < 8; i++) {
        int p = t + i * 128;
        if (p < P_) { float e = expf(v[i] - mx); v[i] = e; sum += e; }
    }
    red[t] = sum; __syncthreads();
    for (int s = 64; s > 0; s >>= 1) {
        if (t < s) red[t] += red[t + s];
        __syncthreads();
    }
    float inv = 1.f / red[0];
#pragma unroll
    for (int i = 0; i < 8; i++) {
        int p = t + i * 128;
        if (p < P_) row[p] = v[i] * inv;
    }
}

__global__ void diag_gather(const float* __restrict__ xo, float* __restrict__ xd)
{
    long idx = (long)blockIdx.x * 256 + threadIdx.x;
    if (idx >= (long)M_ * C_) return;
    int c = (int)(idx & (C_ - 1));
    long m = idx >> 9;
    int s = (int)(m % N_);
    int f = s / P_;
    xd[idx] = xo[((long)m * F_ + f) * C_ + c];
}

__global__ void stage2_attn(const float* __restrict__ q2,
                            const float* __restrict__ kv,
                            float* __restrict__ out2,
                            float* __restrict__ attn2)
{
    int m = blockIdx.x;
    int b = m / N_, s = m % N_;
    int w = threadIdx.x >> 5;
    int l = threadIdx.x & 31;

    const float* qv = q2 + (long)m * C_ + w * DH_;
    float q0 = qv[l], q1 = qv[l + 32];

    float wgt[F_];
    float mx = -1e30f;
#pragma unroll
    for (int f = 0; f < F_; f++) {
        const float* kf = kv + ((long)m * F_ + f) * (2 * C_) + w * DH_;
        float p = q0 * kf[l] + q1 * kf[l + 32];
#pragma unroll
        for (int o = 16; o > 0; o >>= 1) p += __shfl_xor_sync(0xffffffffu, p, o);
        wgt[f] = p;
        mx = fmaxf(mx, p);
    }
    float sum = 0.f;
#pragma unroll
    for (int f = 0; f < F_; f++) { wgt[f] = expf(wgt[f] - mx); sum += wgt[f]; }
    float inv = 1.f / sum;
#pragma unroll
    for (int f = 0; f < F_; f++) wgt[f] *= inv;

    if (l < F_)
        attn2[(((long)b * H_ + w) * N_ + s) * F_ + l] = wgt[l];

    float o0 = 0.f, o1 = 0.f;
#pragma unroll
    for (int f = 0; f < F_; f++) {
        const float* vf = kv + ((long)m * F_ + f) * (2 * C_) + C_ + w * DH_;
        o0 += wgt[f] * vf[l];
        o1 += wgt[f] * vf[l + 32];
    }
    out2[(long)m * C_ + w * DH_ + l]      = o0;
    out2[(long)m * C_ + w * DH_ + l + 32] = o1;
}

__global__ void scatter_out(const float* __restrict__ o,
                            const float* __restrict__ bias,
                            float* __restrict__ out)
{
    long idx = (long)blockIdx.x * 256 + threadIdx.x;
    if (idx >= (long)M_ * C_) return;
    int c = (int)(idx & (C_ - 1));
    long m = idx >> 9;
    int b = (int)(m / N_);
    int s = (int)(m % N_);
    int f = s / P_;
    int p = s % P_;
    out[(long)p * (B_ * F_ * C_) + ((long)b * F_ + f) * C_ + c] = o[idx] + bias[c];
}

// ---------------- host launcher ----------------------------------------------
static void launch_gemm(const float* A, const float* B, float* C,
                        int M, int N, int K, int lda, int ldb, int ldc,
                        int Z, int Z2,
                        long sA1, long sA2, long sB1, long sB2,
                        long sC1, long sC2, float alpha, bool transb)
{
    dim3 grid((N + BN - 1) / BN, (M + BM - 1) / BM, Z);
    if (transb)
        gemm_bf16x3<true><<<grid, 256, SMEM_BYTES>>>(A, B, C, M, N, K, lda, ldb, ldc,
                                                     Z2, sA1, sA2, sB1, sB2, sC1, sC2, alpha);
    else
        gemm_bf16x3<false><<<grid, 256, SMEM_BYTES>>>(A, B, C, M, N, K, lda, ldb, ldc,
                                                      Z2, sA1, sA2, sB1, sB2, sC1, sC2, alpha);
}

extern "C" void kernel_launch(void* const* d_in, const int* in_sizes, int n_in,
                              void* d_out, int out_size)
{
    (void)in_sizes; (void)n_in; (void)out_size;
    const float* x      = (const float*)d_in[0];
    const float* W_qkv  = (const float*)d_in[1];
    const float* W_q2   = (const float*)d_in[2];
    const float* W_kv2  = (const float*)d_in[3];
    const float* W_proj = (const float*)d_in[4];
    const float* b_proj = (const float*)d_in[5];
    float* out = (float*)d_out;

    static bool attr_set = false;
    if (!attr_set) {
        cudaFuncSetAttribute(gemm_bf16x3<true>,
                             cudaFuncAttributeMaxDynamicSharedMemorySize, SMEM_BYTES);
        cudaFuncSetAttribute(gemm_bf16x3<false>,
                             cudaFuncAttributeMaxDynamicSharedMemorySize, SMEM_BYTES);
        attr_set = true;
    }

    float *px, *pqkv, *pscores, *pxo, *pxd, *pq2, *pkv, *po2, *po2p;
    cudaGetSymbolAddress((void**)&px,      g_x);
    cudaGetSymbolAddress((void**)&pqkv,    g_qkv);
    cudaGetSymbolAddress((void**)&pscores, g_scores);
    cudaGetSymbolAddress((void**)&pxo,     g_xo);
    cudaGetSymbolAddress((void**)&pxd,     g_xdiag);
    cudaGetSymbolAddress((void**)&pq2,     g_q2);
    cudaGetSymbolAddress((void**)&pkv,     g_k2v2);
    cudaGetSymbolAddress((void**)&po2,     g_out2);
    cudaGetSymbolAddress((void**)&po2p,    g_out2p);

    const long elems = (long)M_ * C_;
    const int  eb    = (int)((elems + 255) / 256);

    // 1) xb = transpose(x)
    transpose_x<<<eb, 256>>>(x, px);

    // 2) qkv = xb @ W_qkv
    launch_gemm(px, W_qkv, pqkv, M_, 3 * C_, C_, C_, 3 * C_, 3 * C_,
                1, 1, 0, 0, 0, 0, 0, 0, 1.0f, false);

    // 3) scores[b] = scale * Q_b @ K_b^T
    launch_gemm(pqkv, pqkv + C_, pscores, N_, N_, C_, 3 * C_, 3 * C_, N_,
                B_, 1,
                (long)N_ * 3 * C_, 0, (long)N_ * 3 * C_, 0,
                (long)N_ * N_, 0, 0.125f, true);

    // 4) softmax over P within each frame, in place
    softmax_frames<<<M_ * F_, 128>>>(pscores);

    // 5) xo[b,:,f,:] = attn1[b,:,f,:] @ V[b,f]
    launch_gemm(pscores, pqkv + 2 * C_, pxo, N_, C_, P_, N_, 3 * C_, F_ * C_,
                B_ * F_, F_,
                (long)N_ * N_, (long)P_,
                (long)N_ * 3 * C_, (long)P_ * 3 * C_,
                (long)N_ * F_ * C_, (long)C_, 1.0f, false);

    // 6) diagonal gather
    diag_gather<<<eb, 256>>>(pxo, pxd);

    // 7) q2 = (x_diag @ W_q2) * scale
    launch_gemm(pxd, W_q2, pq2, M_, C_, C_, C_, C_, C_,
                1, 1, 0, 0, 0, 0, 0, 0, 0.125f, false);

    // 8) k2|v2 = xo @ W_kv2
    launch_gemm(pxo, W_kv2, pkv, MKV_, 2 * C_, C_, C_, 2 * C_, 2 * C_,
                1, 1, 0, 0, 0, 0, 0, 0, 1.0f, false);

    // 9) temporal attention; attn2 written straight into d_out tail
    stage2_attn<<<M_, 256>>>(pq2, pkv, po2, out + OUT1_);

    // 10) proj
    launch_gemm(po2, W_proj, po2p, M_, C_, C_, C_, C_, C_,
                1, 1, 0, 0, 0, 0, 0, 0, 1.0f, false);

    // 11) bias + output permutation
    scatter_out<<<eb, 256>>>(po2p, b_proj, out);
}

// round 4
// speedup vs baseline: 2.1433x; 1.5567x over previous
#include <cuda_runtime.h>
#include <cuda_bf16.h>

// Problem constants
#define B_  4
#define F_  5
#define P_  920
#define N_  4600          // F_*P_
#define C_  512
#define H_  8
#define DH_ 64
#define M_  (B_*N_)       // 18400
#define MKV_ (M_*F_)      // 92000
#define OUT1_ 9420800     // 920*20*512 (first tuple output element count)

#define KPACK 256         // packets per 512-elem row
#define PP_   460         // packets per 920-elem row

// ---------------- scratch (static device globals; no allocations) -----------
// "split-packet" format: uint2 per k-pair = {bf16 hi(k),hi(k+1) | lo(k),lo(k+1)}
static __device__ uint2 g_xsp   [(size_t)M_ * KPACK];            // x split (B*N, 512)
static __device__ uint2 g_qkvsp [(size_t)M_ * 3 * KPACK];        // q|k|v split
static __device__ float g_scores[(size_t)B_ * N_ * N_];          // fp32 scores
static __device__ uint2 g_attn1sp[(size_t)B_ * N_ * (F_*PP_)];   // attn1 split (k over P)
static __device__ uint2 g_vt    [(size_t)B_ * F_ * C_ * PP_];    // V^T split (rows=c, k over P)
static __device__ uint2 g_xosp  [(size_t)M_ * F_ * KPACK];       // xo split
static __device__ uint2 g_xdsp  [(size_t)M_ * KPACK];            // x_diag split
static __device__ float g_q2    [(size_t)M_ * C_];
static __device__ float g_k2v2  [(size_t)MKV_ * 2 * C_];
static __device__ uint2 g_out2sp[(size_t)M_ * KPACK];
static __device__ uint2 g_wqkvt [1536 * KPACK];                  // W^T split weights
static __device__ uint2 g_wq2t  [ 512 * KPACK];
static __device__ uint2 g_wkv2t [1024 * KPACK];
static __device__ uint2 g_wprojt[ 512 * KPACK];

// ---------------- bf16 split helpers -----------------------------------------
__device__ __forceinline__ unsigned pack_bf2(__nv_bfloat16 a, __nv_bfloat16 b) {
    __nv_bfloat162 t; t.x = a; t.y = b;
    return *reinterpret_cast<unsigned*>(&t);
}
__device__ __forceinline__ uint2 split2(float a, float b) {
    __nv_bfloat16 h0 = __float2bfloat16_rn(a);
    __nv_bfloat16 h1 = __float2bfloat16_rn(b);
    __nv_bfloat16 l0 = __float2bfloat16_rn(a - __bfloat162float(h0));
    __nv_bfloat16 l1 = __float2bfloat16_rn(b - __bfloat162float(h1));
    uint2 e; e.x = pack_bf2(h0, h1); e.y = pack_bf2(l0, l1);
    return e;
}

__device__ __forceinline__ void mma_bf16(float* c, const unsigned* a, const unsigned* b) {
    asm volatile(
        "mma.sync.aligned.m16n8k16.row.col.f32.bf16.bf16.f32 "
        "{%0,%1,%2,%3}, {%4,%5,%6,%7}, {%8,%9}, {%0,%1,%2,%3};"
        : "+f"(c[0]), "+f"(c[1]), "+f"(c[2]), "+f"(c[3])
        : "r"(a[0]), "r"(a[1]), "r"(a[2]), "r"(a[3]),
          "r"(b[0]), "r"(b[1]));
}

// ---------------- pipelined bf16x3 GEMM on pre-split packets ------------------
// C(MxN) = alpha * A(MxK) x B(NxK)^T, A/B are packet arrays (k fastest).
// 128x128x32 tile, 4-stage cp.async pipeline, xor-swizzled smem, 8 warps.
// EPI: 0 = fp32 C, 1 = split-packet C, 2 = proj (bias + (P,B*F,C) permute).
#define STAGES 4
#define TILE_U 2048                       // uint2 per operand tile (128 rows x 16 kp)
#define SMEM_BYTES (STAGES * 2 * TILE_U * 8)   // 131072

// swizzled smem index (uint2 units) for element-packet kp of row r
__device__ __forceinline__ int sidx(int r, int kp) {
    return r * 16 + ((((kp >> 1) ^ (r & 7)) << 1) | (kp & 1));
}

template<int EPI>
__global__ __launch_bounds__(256)
void gemm_sp(const uint2* __restrict__ A,
             const uint2* __restrict__ B,
             void* __restrict__ Cv,
             int M, int N, int K,
             int ldap, int ldbp, int ldc,   // A/B strides in packets, C in elems
             int Z2,
             long sA1, long sA2, long sB1, long sB2,   // packet units
             long sC1, long sC2,                       // elem units
             float alpha, const float* __restrict__ bias)
{
    extern __shared__ __align__(16) unsigned char dsm[];
    uint2* sm = reinterpret_cast<uint2*>(dsm);

    const int z  = blockIdx.z;
    const int zb = z / Z2, zf = z % Z2;
    A += (long)zb * sA1 + (long)zf * sA2;
    B += (long)zb * sB1 + (long)zf * sB2;
    float* Cf = (float*)Cv + (long)zb * sC1 + (long)zf * sC2;

    const int bm = blockIdx.y * 128;
    const int bn = blockIdx.x * 128;
    const int tid  = threadIdx.x;
    const int lane = tid & 31;
    const int gid  = lane >> 2;
    const int tig  = lane & 3;
    const int wid  = tid >> 5;
    const int wm   = wid >> 2;
    const int wn   = wid & 3;

    const int Kp = K >> 1;                 // packets per row
    const int kt = (Kp + 15) >> 4;         // k-tiles of 16 packets

    float acc[4][4][4];
#pragma unroll
    for (int i = 0; i < 4; i++)
#pragma unroll
        for (int j = 0; j < 4; j++)
#pragma unroll
            for (int t = 0; t < 4; t++) acc[i][j][t] = 0.f;

    // issue one stage of cp.async loads (A + B), 16B chunks with zfill guards
    auto issue = [&](int buf, int ktile) {
        uint2* sA = sm + buf * (2 * TILE_U);
        uint2* sB = sA + TILE_U;
        const int kp0 = ktile * 16;
#pragma unroll
        for (int i = 0; i < 4; i++) {
            int lin = i * 256 + tid;
            int row = lin >> 3, ch = lin & 7;
            int grow = bm + row;
            int gkp  = kp0 + ch * 2;
            bool v = (grow < M) && (gkp < Kp);
            const uint2* src = A + (long)(v ? grow : 0) * ldap + (v ? gkp : 0);
            unsigned sa = (unsigned)__cvta_generic_to_shared(
                &sA[row * 16 + ((ch ^ (row & 7)) << 1)]);
            unsigned sz = v ? 16u : 0u;
            asm volatile("cp.async.cg.shared.global [%0], [%1], 16, %2;\n"
                         :: "r"(sa), "l"(src), "r"(sz));
        }
#pragma unroll
        for (int i = 0; i < 4; i++) {
            int lin = i * 256 + tid;
            int row = lin >> 3, ch = lin & 7;
            int grow = bn + row;
            int gkp  = kp0 + ch * 2;
            bool v = (grow < N) && (gkp < Kp);
            const uint2* src = B + (long)(v ? grow : 0) * ldbp + (v ? gkp : 0);
            unsigned sa = (unsigned)__cvta_generic_to_shared(
                &sB[row * 16 + ((ch ^ (row & 7)) << 1)]);
            unsigned sz = v ? 16u : 0u;
            asm volatile("cp.async.cg.shared.global [%0], [%1], 16, %2;\n"
                         :: "r"(sa), "l"(src), "r"(sz));
        }
        asm volatile("cp.async.commit_group;\n" ::: "memory");
    };

    // prologue: STAGES-1 tiles in flight
    issue(0, 0);
    issue(1, 1);
    issue(2, 2);

    const int r0 = wm * 64 + gid;
    const int c0 = wn * 32 + gid;

    for (int it = 0; it < kt; it++) {
        asm volatile("cp.async.wait_group 2;\n" ::: "memory");
        __syncthreads();

        if (it + 3 < kt) issue((it + 3) & 3, it + 3);
        else asm volatile("cp.async.commit_group;\n" ::: "memory");

        const uint2* sA = sm + (it & 3) * (2 * TILE_U);
        const uint2* sB = sA + TILE_U;

#pragma unroll
        for (int ks = 0; ks < 2; ks++) {
            const int kpb = ks * 8;
            unsigned ah[4][4], al[4][4], bh[4][2], bl[4][2];
#pragma unroll
            for (int mt = 0; mt < 4; mt++) {
                int r = r0 + mt * 16;
                uint2 e00 = sA[sidx(r,     kpb + tig)];
                uint2 e10 = sA[sidx(r + 8, kpb + tig)];
                uint2 e01 = sA[sidx(r,     kpb + tig + 4)];
                uint2 e11 = sA[sidx(r + 8, kpb + tig + 4)];
                ah[mt][0] = e00.x; ah[mt][1] = e10.x; ah[mt][2] = e01.x; ah[mt][3] = e11.x;
                al[mt][0] = e00.y; al[mt][1] = e10.y; al[mt][2] = e01.y; al[mt][3] = e11.y;
            }
#pragma unroll
            for (int nt = 0; nt < 4; nt++) {
                int c = c0 + nt * 8;
                uint2 f0 = sB[sidx(c, kpb + tig)];
                uint2 f1 = sB[sidx(c, kpb + tig + 4)];
                bh[nt][0] = f0.x; bh[nt][1] = f1.x;
                bl[nt][0] = f0.y; bl[nt][1] = f1.y;
            }
#pragma unroll
            for (int mt = 0; mt < 4; mt++)
#pragma unroll
                for (int nt = 0; nt < 4; nt++) {
                    mma_bf16(acc[mt][nt], al[mt], bh[nt]);
                    mma_bf16(acc[mt][nt], ah[mt], bl[nt]);
                    mma_bf16(acc[mt][nt], ah[mt], bh[nt]);
                }
        }
        __syncthreads();
    }

    // ---- epilogue ----
#pragma unroll
    for (int mt = 0; mt < 4; mt++) {
#pragma unroll
        for (int nt = 0; nt < 4; nt++) {
            int row = bm + wm * 64 + mt * 16 + gid;
            int col = bn + wn * 32 + nt * 8 + tig * 2;
            float v0 = alpha * acc[mt][nt][0];
            float v1 = alpha * acc[mt][nt][1];
            float v2 = alpha * acc[mt][nt][2];
            float v3 = alpha * acc[mt][nt][3];
            if (EPI == 0) {
                if (row < M) {
                    if (col < N)     Cf[(long)row * ldc + col]     = v0;
                    if (col + 1 < N) Cf[(long)row * ldc + col + 1] = v1;
                }
                if (row + 8 < M) {
                    if (col < N)     Cf[(long)(row + 8) * ldc + col]     = v2;
                    if (col + 1 < N) Cf[(long)(row + 8) * ldc + col + 1] = v3;
                }
            } else if (EPI == 1) {
                uint2* Cp = reinterpret_cast<uint2*>(Cf);
                int ldcp = ldc >> 1;
                if (row < M && col < N)
                    Cp[(long)row * ldcp + (col >> 1)] = split2(v0, v1);
                if (row + 8 < M && col < N)
                    Cp[(long)(row + 8) * ldcp + (col >> 1)] = split2(v2, v3);
            } else {
                // proj: out[p, b*F+f, c] = v + bias[c]
                if (row < M && col < N) {
                    int b = row / N_, s = row % N_;
                    int f = s / P_,  p = s % P_;
                    float* o = Cf + (long)p * (B_ * F_ * C_) + ((long)b * F_ + f) * C_ + col;
                    o[0] = v0 + bias[col];
                    o[1] = v1 + bias[col + 1];
                }
                if (row + 8 < M && col < N) {
                    int r2 = row + 8;
                    int b = r2 / N_, s = r2 % N_;
                    int f = s / P_,  p = s % P_;
                    float* o = Cf + (long)p * (B_ * F_ * C_) + ((long)b * F_ + f) * C_ + col;
                    o[0] = v2 + bias[col];
                    o[1] = v3 + bias[col + 1];
                }
            }
        }
    }
}

// ---------------- producer / glue kernels ------------------------------------
// x (S, B0, C) -> split packets (B*N, C)
__global__ void transpose_x_sp(const float* __restrict__ x, uint2* __restrict__ o)
{
    long idx = (long)blockIdx.x * 256 + threadIdx.x;
    if (idx >= (long)M_ * KPACK) return;
    int pk = (int)(idx & (KPACK - 1));
    long m = idx >> 8;
    int b = (int)(m / N_);
    int n = (int)(m % N_);
    float2 v = *reinterpret_cast<const float2*>(&x[((long)n * B_ + b) * C_ + pk * 2]);
    o[idx] = split2(v.x, v.y);
}

// W (K=512, Ncols) -> W^T split packets (Ncols, 256)
__global__ void wsplit(const float* __restrict__ W, uint2* __restrict__ o, int Ncols)
{
    long idx = (long)blockIdx.x * 256 + threadIdx.x;
    if (idx >= (long)Ncols * KPACK) return;
    int n  = (int)(idx % Ncols);
    int kp = (int)(idx / Ncols);
    float a = W[(long)(2 * kp)     * Ncols + n];
    float b = W[(long)(2 * kp + 1) * Ncols + n];
    o[(long)n * KPACK + kp] = split2(a, b);
}

// v part of qkv packets -> V^T split packets, rows=c, k over P (per b,f)
__global__ void vtrans(const uint2* __restrict__ qkv, uint2* __restrict__ vt)
{
    long idx = (long)blockIdx.x * 256 + threadIdx.x;
    if (idx >= (long)B_ * F_ * PP_ * C_) return;
    int c  = (int)(idx & (C_ - 1));
    long r = idx >> 9;
    int pp = (int)(r % PP_);
    int bf = (int)(r / PP_);
    int b = bf / F_, f = bf % F_;
    long row0 = (long)b * N_ + (long)f * P_ + 2 * pp;
    const ushort4* s0 = reinterpret_cast<const ushort4*>(&qkv[row0 * (3 * KPACK) + 2 * KPACK + (c >> 1)]);
    const ushort4* s1 = reinterpret_cast<const ushort4*>(&qkv[(row0 + 1) * (3 * KPACK) + 2 * KPACK + (c >> 1)]);
    ushort4 a = *s0, e = *s1;
    ushort4 r4;
    if (c & 1) { r4.x = a.y; r4.y = e.y; r4.z = a.w; r4.w = e.w; }
    else       { r4.x = a.x; r4.y = e.x; r4.z = a.z; r4.w = e.z; }
    *reinterpret_cast<ushort4*>(&vt[((long)bf * C_ + c) * PP_ + pp]) = r4;
}

// softmax over P within each (b,q,f) row; fp32 in -> split packets out
__global__ void softmax_frames_sp(const float* __restrict__ sc, uint2* __restrict__ at)
{
    int rid = blockIdx.x;
    long bq = rid / F_;
    int  f  = rid % F_;
    const float2* row = reinterpret_cast<const float2*>(sc + bq * (long)N_ + (long)f * P_);
    uint2* orow = at + bq * (long)(F_ * PP_) + (long)f * PP_;
    int t = threadIdx.x;

    float2 v[4];
    float mx = -1e30f;
#pragma unroll
    for (int i = 0; i < 4; i++) {
        int pp = t + i * 128;
        if (pp < PP_) { v[i] = row[pp]; mx = fmaxf(mx, fmaxf(v[i].x, v[i].y)); }
        else v[i] = make_float2(-1e30f, -1e30f);
    }
    __shared__ float red[128];
    red[t] = mx; __syncthreads();
    for (int s = 64; s > 0; s >>= 1) {
        if (t < s) red[t] = fmaxf(red[t], red[t + s]);
        __syncthreads();
    }
    mx = red[0];
    __syncthreads();

    float sum = 0.f;
#pragma unroll
    for (int i = 0; i < 4; i++) {
        int pp = t + i * 128;
        if (pp < PP_) {
            v[i].x = expf(v[i].x - mx);
            v[i].y = expf(v[i].y - mx);
            sum += v[i].x + v[i].y;
        }
    }
    red[t] = sum; __syncthreads();
    for (int s = 64; s > 0; s >>= 1) {
        if (t < s) red[t] += red[t + s];
        __syncthreads();
    }
    float inv = 1.f / red[0];
#pragma unroll
    for (int i = 0; i < 4; i++) {
        int pp = t + i * 128;
        if (pp < PP_) orow[pp] = split2(v[i].x * inv, v[i].y * inv);
    }
}

// x_diag packets: row m <- xo row (m, f(m))
__global__ void diag_gather_sp(const uint2* __restrict__ xo, uint2* __restrict__ xd)
{
    long idx = (long)blockIdx.x * 256 + threadIdx.x;
    if (idx >= (long)M_ * KPACK) return;
    int pk = (int)(idx & (KPACK - 1));
    long m = idx >> 8;
    int f = (int)((m % N_) / P_);
    xd[idx] = xo[(m * F_ + f) * KPACK + pk];
}

// Stage-2 temporal attention; out2 as split packets, attn2 fp32 into d_out tail.
__global__ void stage2_attn(const float* __restrict__ q2,
                            const float* __restrict__ kv,
                            uint2* __restrict__ out2,
                            float* __restrict__ attn2)
{
    int m = blockIdx.x;
    int b = m / N_, s = m % N_;
    int w = threadIdx.x >> 5;
    int l = threadIdx.x & 31;

    const float2* qv = reinterpret_cast<const float2*>(q2 + (long)m * C_ + w * DH_);
    float2 q = qv[l];

    float wgt[F_];
    float mx = -1e30f;
#pragma unroll
    for (int f = 0; f < F_; f++) {
        const float2* kf = reinterpret_cast<const float2*>(
            kv + ((long)m * F_ + f) * (2 * C_) + w * DH_);
        float2 kk = kf[l];
        float p = q.x * kk.x + q.y * kk.y;
#pragma unroll
        for (int o = 16; o > 0; o >>= 1) p += __shfl_xor_sync(0xffffffffu, p, o);
        wgt[f] = p;
        mx = fmaxf(mx, p);
    }
    float sum = 0.f;
#pragma unroll
    for (int f = 0; f < F_; f++) { wgt[f] = expf(wgt[f] - mx); sum += wgt[f]; }
    float inv = 1.f / sum;
#pragma unroll
    for (int f = 0; f < F_; f++) wgt[f] *= inv;

#pragma unroll
    for (int f = 0; f < F_; f++)
        if (l == f)
            attn2[(((long)b * H_ + w) * N_ + s) * F_ + f] = wgt[f];

    float o0 = 0.f, o1 = 0.f;
#pragma unroll
    for (int f = 0; f < F_; f++) {
        const float2* vf = reinterpret_cast<const float2*>(
            kv + ((long)m * F_ + f) * (2 * C_) + C_ + w * DH_);
        float2 vv = vf[l];
        o0 += wgt[f] * vv.x;
        o1 += wgt[f] * vv.y;
    }
    out2[(long)m * KPACK + w * 32 + l] = split2(o0, o1);
}

// ---------------- host launcher ----------------------------------------------
template<int EPI>
static void launch_gemm(const uint2* A, const uint2* B, void* C,
                        int M, int N, int K, int ldap, int ldbp, int ldc,
                        int Z, int Z2,
                        long sA1, long sA2, long sB1, long sB2,
                        long sC1, long sC2, float alpha, const float* bias)
{
    dim3 grid((N + 127) / 128, (M + 127) / 128, Z);
    gemm_sp<EPI><<<grid, 256, SMEM_BYTES>>>(A, B, C, M, N, K, ldap, ldbp, ldc,
                                            Z2, sA1, sA2, sB1, sB2, sC1, sC2,
                                            alpha, bias);
}

extern "C" void kernel_launch(void* const* d_in, const int* in_sizes, int n_in,
                              void* d_out, int out_size)
{
    (void)in_sizes; (void)n_in; (void)out_size;
    const float* x      = (const float*)d_in[0];
    const float* W_qkv  = (const float*)d_in[1];
    const float* W_q2   = (const float*)d_in[2];
    const float* W_kv2  = (const float*)d_in[3];
    const float* W_proj = (const float*)d_in[4];
    const float* b_proj = (const float*)d_in[5];
    float* out = (float*)d_out;

    static bool attr_set = false;
    if (!attr_set) {
        cudaFuncSetAttribute(gemm_sp<0>, cudaFuncAttributeMaxDynamicSharedMemorySize, SMEM_BYTES);
        cudaFuncSetAttribute(gemm_sp<1>, cudaFuncAttributeMaxDynamicSharedMemorySize, SMEM_BYTES);
        cudaFuncSetAttribute(gemm_sp<2>, cudaFuncAttributeMaxDynamicSharedMemorySize, SMEM_BYTES);
        attr_set = true;
    }

    uint2 *pxsp, *pqkvsp, *pattn1, *pvt, *pxosp, *pxdsp, *pout2sp;
    uint2 *pwqkvt, *pwq2t, *pwkv2t, *pwprojt;
    float *pscores, *pq2, *pkv;
    cudaGetSymbolAddress((void**)&pxsp,    g_xsp);
    cudaGetSymbolAddress((void**)&pqkvsp,  g_qkvsp);
    cudaGetSymbolAddress((void**)&pscores, g_scores);
    cudaGetSymbolAddress((void**)&pattn1,  g_attn1sp);
    cudaGetSymbolAddress((void**)&pvt,     g_vt);
    cudaGetSymbolAddress((void**)&pxosp,   g_xosp);
    cudaGetSymbolAddress((void**)&pxdsp,   g_xdsp);
    cudaGetSymbolAddress((void**)&pq2,     g_q2);
    cudaGetSymbolAddress((void**)&pkv,     g_k2v2);
    cudaGetSymbolAddress((void**)&pout2sp, g_out2sp);
    cudaGetSymbolAddress((void**)&pwqkvt,  g_wqkvt);
    cudaGetSymbolAddress((void**)&pwq2t,   g_wq2t);
    cudaGetSymbolAddress((void**)&pwkv2t,  g_wkv2t);
    cudaGetSymbolAddress((void**)&pwprojt, g_wprojt);

    const int pb = (int)(((long)M_ * KPACK + 255) / 256);

    // 0) weight transposes + splits (small)
    wsplit<<<(1536 * KPACK + 255) / 256, 256>>>(W_qkv,  pwqkvt, 1536);
    wsplit<<<( 512 * KPACK + 255) / 256, 256>>>(W_q2,   pwq2t,   512);
    wsplit<<<(1024 * KPACK + 255) / 256, 256>>>(W_kv2,  pwkv2t, 1024);
    wsplit<<<( 512 * KPACK + 255) / 256, 256>>>(W_proj, pwprojt, 512);

    // 1) xb -> split packets
    transpose_x_sp<<<pb, 256>>>(x, pxsp);

    // 2) qkv = xb @ W_qkv -> split packets
    launch_gemm<1>(pxsp, pwqkvt, pqkvsp, M_, 3 * C_, C_, KPACK, KPACK, 3 * C_,
                   1, 1, 0, 0, 0, 0, 0, 0, 1.0f, nullptr);

    // 3) scores[b] = scale * Q_b @ K_b^T  (fp32)
    launch_gemm<0>(pqkvsp, pqkvsp + KPACK, pscores, N_, N_, C_,
                   3 * KPACK, 3 * KPACK, N_, B_, 1,
                   (long)N_ * 3 * KPACK, 0, (long)N_ * 3 * KPACK, 0,
                   (long)N_ * N_, 0, 0.125f, nullptr);

    // 4) softmax over P -> attn1 split packets
    softmax_frames_sp<<<M_ * F_, 128>>>(pscores, pattn1);

    // 5) V^T split packets
    vtrans<<<(int)(((long)B_ * F_ * PP_ * C_ + 255) / 256), 256>>>(pqkvsp, pvt);

    // 6) xo[b,:,f,:] = attn1[b,:,f,:] @ V[b,f] -> split packets
    launch_gemm<1>(pattn1, pvt, pxosp, N_, C_, P_,
                   F_ * PP_, PP_, F_ * C_, B_ * F_, F_,
                   (long)N_ * F_ * PP_, (long)PP_,
                   (long)F_ * C_ * PP_, (long)C_ * PP_,
                   (long)N_ * F_ * C_, (long)C_, 1.0f, nullptr);

    // 7) diagonal gather (packets)
    diag_gather_sp<<<pb, 256>>>(pxosp, pxdsp);

    // 8) q2 = (x_diag @ W_q2) * scale  (fp32)
    launch_gemm<0>(pxdsp, pwq2t, pq2, M_, C_, C_, KPACK, KPACK, C_,
                   1, 1, 0, 0, 0, 0, 0, 0, 0.125f, nullptr);

    // 9) k2|v2 = xo @ W_kv2  (fp32)
    launch_gemm<0>(pxosp, pwkv2t, pkv, MKV_, 2 * C_, C_, KPACK, KPACK, 2 * C_,
                   1, 1, 0, 0, 0, 0, 0, 0, 1.0f, nullptr);

    // 10) temporal attention; attn2 straight into d_out tail
    stage2_attn<<<M_, 256>>>(pq2, pkv, pout2sp, out + OUT1_);

    // 11) proj + bias + output permutation fused
    launch_gemm<2>(pout2sp, pwprojt, out, M_, C_, C_, KPACK, KPACK, C_,
                   1, 1, 0, 0, 0, 0, 0, 0, 1.0f, b_proj);
}

// round 6
// speedup vs baseline: 2.1794x; 1.0169x over previous
#include <cuda_runtime.h>
#include <cuda_bf16.h>

// Problem constants
#define B_  4
#define F_  5
#define P_  920
#define N_  4600          // F_*P_
#define C_  512
#define H_  8
#define DH_ 64
#define M_  (B_*N_)       // 18400
#define MKV_ (M_*F_)      // 92000
#define OUT1_ 9420800     // first tuple output element count

#define KPACK 256         // packets per 512-elem row
#define PP_   460         // packets per 920-elem row

// ---------------- scratch (static device globals; no allocations) -----------
// "split-packet" format: uint2 per k-pair = {bf16 hi(k),hi(k+1) | lo(k),lo(k+1)}
static __device__ uint2 g_xsp   [(size_t)M_ * KPACK];
static __device__ uint2 g_qkvsp [(size_t)M_ * 3 * KPACK];
static __device__ float g_scores[(size_t)B_ * N_ * N_];
static __device__ uint2 g_attn1sp[(size_t)B_ * N_ * (F_*PP_)];
static __device__ uint2 g_vt    [(size_t)B_ * F_ * C_ * PP_];
static __device__ uint2 g_xosp  [(size_t)M_ * F_ * KPACK];
static __device__ uint2 g_xdsp  [(size_t)M_ * KPACK];
static __device__ float g_q2    [(size_t)M_ * C_];
static __device__ float g_k2v2  [(size_t)MKV_ * 2 * C_];
static __device__ uint2 g_out2sp[(size_t)M_ * KPACK];
static __device__ uint2 g_wqkvt [1536 * KPACK];
static __device__ uint2 g_wq2t  [ 512 * KPACK];
static __device__ uint2 g_wkv2t [1024 * KPACK];
static __device__ uint2 g_wprojt[ 512 * KPACK];

// ---------------- bf16 split helpers -----------------------------------------
__device__ __forceinline__ unsigned pack_bf2(__nv_bfloat16 a, __nv_bfloat16 b) {
    __nv_bfloat162 t; t.x = a; t.y = b;
    return *reinterpret_cast<unsigned*>(&t);
}
__device__ __forceinline__ uint2 split2(float a, float b) {
    __nv_bfloat16 h0 = __float2bfloat16_rn(a);
    __nv_bfloat16 h1 = __float2bfloat16_rn(b);
    __nv_bfloat16 l0 = __float2bfloat16_rn(a - __bfloat162float(h0));
    __nv_bfloat16 l1 = __float2bfloat16_rn(b - __bfloat162float(h1));
    uint2 e; e.x = pack_bf2(h0, h1); e.y = pack_bf2(l0, l1);
    return e;
}

__device__ __forceinline__ void mma_bf16(float* c, const unsigned* a, const unsigned* b) {
    asm volatile(
        "mma.sync.aligned.m16n8k16.row.col.f32.bf16.bf16.f32 "
        "{%0,%1,%2,%3}, {%4,%5,%6,%7}, {%8,%9}, {%0,%1,%2,%3};"
        : "+f"(c[0]), "+f"(c[1]), "+f"(c[2]), "+f"(c[3])
        : "r"(a[0]), "r"(a[1]), "r"(a[2]), "r"(a[3]),
          "r"(b[0]), "r"(b[1]));
}

// ---------------- pipelined bf16x3 GEMM on pre-split packets ------------------
// C(MxN) = alpha * A(MxK) x B(NxK)^T. Block 128x256x32, warp tile 64x64,
// 8 warps (2x4), 3-stage cp.async pipeline, xor-swizzled smem.
// EPI: 0 = fp32 C, 1 = split-packet C, 2 = proj (bias + (P,B*F,C) permute).
#define STAGES   3
#define TILE_A_U 2048                     // 128 rows x 16 kp (uint2)
#define TILE_B_U 4096                     // 256 rows x 16 kp
#define STAGE_U  (TILE_A_U + TILE_B_U)    // 6144
#define SMEM_BYTES (STAGES * STAGE_U * 8) // 147456

__device__ __forceinline__ int sidx(int r, int kp) {
    return r * 16 + ((((kp >> 1) ^ (r & 7)) << 1) | (kp & 1));
}

template<int EPI>
__global__ __launch_bounds__(256)
void gemm_sp(const uint2* __restrict__ A,
             const uint2* __restrict__ B,
             void* __restrict__ Cv,
             int M, int N, int K,
             int ldap, int ldbp, int ldc,
             int Z2,
             long sA1, long sA2, long sB1, long sB2,
             long sC1, long sC2,
             float alpha, const float* __restrict__ bias)
{
    extern __shared__ __align__(16) unsigned char dsm[];
    uint2* sm = reinterpret_cast<uint2*>(dsm);

    const int z  = blockIdx.z;
    const int zb = z / Z2, zf = z % Z2;
    A += (long)zb * sA1 + (long)zf * sA2;
    B += (long)zb * sB1 + (long)zf * sB2;
    float* Cf = (float*)Cv + (long)zb * sC1 + (long)zf * sC2;

    const int bm = blockIdx.y * 128;
    const int bn = blockIdx.x * 256;
    const int tid  = threadIdx.x;
    const int lane = tid & 31;
    const int gid  = lane >> 2;
    const int tig  = lane & 3;
    const int wid  = tid >> 5;
    const int wm   = wid >> 2;            // 0..1  (64-row slab)
    const int wn   = wid & 3;             // 0..3  (64-col slab)

    const int Kp = K >> 1;
    const int kt = (Kp + 15) >> 4;

    float acc[4][8][4];
#pragma unroll
    for (int i = 0; i < 4; i++)
#pragma unroll
        for (int j = 0; j < 8; j++)
#pragma unroll
            for (int t = 0; t < 4; t++) acc[i][j][t] = 0.f;

    auto issue = [&](int buf, int ktile) {
        uint2* sA = sm + buf * STAGE_U;
        uint2* sB = sA + TILE_A_U;
        const int kp0 = ktile * 16;
        // A: 128 rows x 8 chunks of 16B -> 1024 chunks, 4/thread
#pragma unroll
        for (int i = 0; i < 4; i++) {
            int lin = i * 256 + tid;
            int row = lin >> 3, ch = lin & 7;
            int grow = bm + row;
            int gkp  = kp0 + ch * 2;
            bool v = (grow < M) && (gkp < Kp);
            const uint2* src = A + (long)(v ? grow : 0) * ldap + (v ? gkp : 0);
            unsigned sa = (unsigned)__cvta_generic_to_shared(
                &sA[row * 16 + ((ch ^ (row & 7)) << 1)]);
            unsigned sz = v ? 16u : 0u;
            asm volatile("cp.async.cg.shared.global [%0], [%1], 16, %2;\n"
                         :: "r"(sa), "l"(src), "r"(sz));
        }
        // B: 256 rows x 8 chunks -> 2048 chunks, 8/thread
#pragma unroll
        for (int i = 0; i < 8; i++) {
            int lin = i * 256 + tid;
            int row = lin >> 3, ch = lin & 7;
            int grow = bn + row;
            int gkp  = kp0 + ch * 2;
            bool v = (grow < N) && (gkp < Kp);
            const uint2* src = B + (long)(v ? grow : 0) * ldbp + (v ? gkp : 0);
            unsigned sa = (unsigned)__cvta_generic_to_shared(
                &sB[row * 16 + ((ch ^ (row & 7)) << 1)]);
            unsigned sz = v ? 16u : 0u;
            asm volatile("cp.async.cg.shared.global [%0], [%1], 16, %2;\n"
                         :: "r"(sa), "l"(src), "r"(sz));
        }
        asm volatile("cp.async.commit_group;\n" ::: "memory");
    };

    issue(0, 0);
    if (kt > 1) issue(1, 1); else asm volatile("cp.async.commit_group;\n" ::: "memory");

    const int r0 = wm * 64 + gid;
    const int c0 = wn * 64 + gid;

    int buf = 0;
    for (int it = 0; it < kt; it++) {
        asm volatile("cp.async.wait_group 1;\n" ::: "memory");
        __syncthreads();

        if (it + 2 < kt) issue((buf + 2) % STAGES, it + 2);
        else asm volatile("cp.async.commit_group;\n" ::: "memory");

        const uint2* sA = sm + buf * STAGE_U;
        const uint2* sB = sA + TILE_A_U;

#pragma unroll
        for (int ks = 0; ks < 2; ks++) {
            const int kpb = ks * 8;
            unsigned ah[4][4], al[4][4];
#pragma unroll
            for (int mt = 0; mt < 4; mt++) {
                int r = r0 + mt * 16;
                uint2 e00 = sA[sidx(r,     kpb + tig)];
                uint2 e10 = sA[sidx(r + 8, kpb + tig)];
                uint2 e01 = sA[sidx(r,     kpb + tig + 4)];
                uint2 e11 = sA[sidx(r + 8, kpb + tig + 4)];
                ah[mt][0] = e00.x; ah[mt][1] = e10.x; ah[mt][2] = e01.x; ah[mt][3] = e11.x;
                al[mt][0] = e00.y; al[mt][1] = e10.y; al[mt][2] = e01.y; al[mt][3] = e11.y;
            }
#pragma unroll
            for (int nt = 0; nt < 8; nt++) {
                int c = c0 + nt * 8;
                uint2 f0 = sB[sidx(c, kpb + tig)];
                uint2 f1 = sB[sidx(c, kpb + tig + 4)];
                unsigned bh[2] = { f0.x, f1.x };
                unsigned bl[2] = { f0.y, f1.y };
#pragma unroll
                for (int mt = 0; mt < 4; mt++) {
                    mma_bf16(acc[mt][nt], al[mt], bh);
                    mma_bf16(acc[mt][nt], ah[mt], bl);
                    mma_bf16(acc[mt][nt], ah[mt], bh);
                }
            }
        }
        buf++; if (buf == STAGES) buf = 0;
    }

    // ---- epilogue ----
#pragma unroll
    for (int mt = 0; mt < 4; mt++) {
#pragma unroll
        for (int nt = 0; nt < 8; nt++) {
            int row = bm + wm * 64 + mt * 16 + gid;
            int col = bn + wn * 64 + nt * 8 + tig * 2;
            float v0 = alpha * acc[mt][nt][0];
            float v1 = alpha * acc[mt][nt][1];
            float v2 = alpha * acc[mt][nt][2];
            float v3 = alpha * acc[mt][nt][3];
            if (EPI == 0) {
                if (row < M) {
                    if (col < N)     Cf[(long)row * ldc + col]     = v0;
                    if (col + 1 < N) Cf[(long)row * ldc + col + 1] = v1;
                }
                if (row + 8 < M) {
                    if (col < N)     Cf[(long)(row + 8) * ldc + col]     = v2;
                    if (col + 1 < N) Cf[(long)(row + 8) * ldc + col + 1] = v3;
                }
            } else if (EPI == 1) {
                uint2* Cp = reinterpret_cast<uint2*>(Cf);
                int ldcp = ldc >> 1;
                if (row < M && col < N)
                    Cp[(long)row * ldcp + (col >> 1)] = split2(v0, v1);
                if (row + 8 < M && col < N)
                    Cp[(long)(row + 8) * ldcp + (col >> 1)] = split2(v2, v3);
            } else {
                if (row < M && col < N) {
                    int b = row / N_, s = row % N_;
                    int f = s / P_,  p = s % P_;
                    float* o = Cf + (long)p * (B_ * F_ * C_) + ((long)b * F_ + f) * C_ + col;
                    o[0] = v0 + bias[col];
                    o[1] = v1 + bias[col + 1];
                }
                if (row + 8 < M && col < N) {
                    int r2 = row + 8;
                    int b = r2 / N_, s = r2 % N_;
                    int f = s / P_,  p = s % P_;
                    float* o = Cf + (long)p * (B_ * F_ * C_) + ((long)b * F_ + f) * C_ + col;
                    o[0] = v2 + bias[col];
                    o[1] = v3 + bias[col + 1];
                }
            }
        }
    }
}

// ---------------- producer / glue kernels ------------------------------------
__global__ void transpose_x_sp(const float* __restrict__ x, uint2* __restrict__ o)
{
    long idx = (long)blockIdx.x * 256 + threadIdx.x;
    if (idx >= (long)M_ * KPACK) return;
    int pk = (int)(idx & (KPACK - 1));
    long m = idx >> 8;
    int b = (int)(m / N_);
    int n = (int)(m % N_);
    float2 v = *reinterpret_cast<const float2*>(&x[((long)n * B_ + b) * C_ + pk * 2]);
    o[idx] = split2(v.x, v.y);
}

__global__ void wsplit(const float* __restrict__ W, uint2* __restrict__ o, int Ncols)
{
    long idx = (long)blockIdx.x * 256 + threadIdx.x;
    if (idx >= (long)Ncols * KPACK) return;
    int n  = (int)(idx % Ncols);
    int kp = (int)(idx / Ncols);
    float a = W[(long)(2 * kp)     * Ncols + n];
    float b = W[(long)(2 * kp + 1) * Ncols + n];
    o[(long)n * KPACK + kp] = split2(a, b);
}

__global__ void vtrans(const uint2* __restrict__ qkv, uint2* __restrict__ vt)
{
    long idx = (long)blockIdx.x * 256 + threadIdx.x;
    if (idx >= (long)B_ * F_ * PP_ * C_) return;
    int c  = (int)(idx & (C_ - 1));
    long r = idx >> 9;
    int pp = (int)(r % PP_);
    int bf = (int)(r / PP_);
    int b = bf / F_, f = bf % F_;
    long row0 = (long)b * N_ + (long)f * P_ + 2 * pp;
    const ushort4* s0 = reinterpret_cast<const ushort4*>(&qkv[row0 * (3 * KPACK) + 2 * KPACK + (c >> 1)]);
    const ushort4* s1 = reinterpret_cast<const ushort4*>(&qkv[(row0 + 1) * (3 * KPACK) + 2 * KPACK + (c >> 1)]);
    ushort4 a = *s0, e = *s1;
    ushort4 r4;
    if (c & 1) { r4.x = a.y; r4.y = e.y; r4.z = a.w; r4.w = e.w; }
    else       { r4.x = a.x; r4.y = e.x; r4.z = a.z; r4.w = e.z; }
    *reinterpret_cast<ushort4*>(&vt[((long)bf * C_ + c) * PP_ + pp]) = r4;
}

__global__ void softmax_frames_sp(const float* __restrict__ sc, uint2* __restrict__ at)
{
    int rid = blockIdx.x;
    long bq = rid / F_;
    int  f  = rid % F_;
    const float2* row = reinterpret_cast<const float2*>(sc + bq * (long)N_ + (long)f * P_);
    uint2* orow = at + bq * (long)(F_ * PP_) + (long)f * PP_;
    int t = threadIdx.x;

    float2 v[4];
    float mx = -1e30f;
#pragma unroll
    for (int i = 0; i < 4; i++) {
        int pp = t + i * 128;
        if (pp < PP_) { v[i] = row[pp]; mx = fmaxf(mx, fmaxf(v[i].x, v[i].y)); }
        else v[i] = make_float2(-1e30f, -1e30f);
    }
    __shared__ float red[128];
    red[t] = mx; __syncthreads();
    for (int s = 64; s > 0; s >>= 1) {
        if (t < s) red[t] = fmaxf(red[t], red[t + s]);
        __syncthreads();
    }
    mx = red[0];
    __syncthreads();

    float sum = 0.f;
#pragma unroll
    for (int i = 0; i < 4; i++) {
        int pp = t + i * 128;
        if (pp < PP_) {
            v[i].x = expf(v[i].x - mx);
            v[i].y = expf(v[i].y - mx);
            sum += v[i].x + v[i].y;
        }
    }
    red[t] = sum; __syncthreads();
    for (int s = 64; s > 0; s >>= 1) {
        if (t < s) red[t] += red[t + s];
        __syncthreads();
    }
    float inv = 1.f / red[0];
#pragma unroll
    for (int i = 0; i < 4; i++) {
        int pp = t + i * 128;
        if (pp < PP_) orow[pp] = split2(v[i].x * inv, v[i].y * inv);
    }
}

__global__ void diag_gather_sp(const uint2* __restrict__ xo, uint2* __restrict__ xd)
{
    long idx = (long)blockIdx.x * 256 + threadIdx.x;
    if (idx >= (long)M_ * KPACK) return;
    int pk = (int)(idx & (KPACK - 1));
    long m = idx >> 8;
    int f = (int)((m % N_) / P_);
    xd[idx] = xo[(m * F_ + f) * KPACK + pk];
}

__global__ void stage2_attn(const float* __restrict__ q2,
                            const float* __restrict__ kv,
                            uint2* __restrict__ out2,
                            float* __restrict__ attn2)
{
    int m = blockIdx.x;
    int b = m / N_, s = m % N_;
    int w = threadIdx.x >> 5;
    int l = threadIdx.x & 31;

    const float2* qv = reinterpret_cast<const float2*>(q2 + (long)m * C_ + w * DH_);
    float2 q = qv[l];

    float wgt[F_];
    float mx = -1e30f;
#pragma unroll
    for (int f = 0; f < F_; f++) {
        const float2* kf = reinterpret_cast<const float2*>(
            kv + ((long)m * F_ + f) * (2 * C_) + w * DH_);
        float2 kk = kf[l];
        float p = q.x * kk.x + q.y * kk.y;
#pragma unroll
        for (int o = 16; o > 0; o >>= 1) p += __shfl_xor_sync(0xffffffffu, p, o);
        wgt[f] = p;
        mx = fmaxf(mx, p);
    }
    float sum = 0.f;
#pragma unroll
    for (int f = 0; f < F_; f++) { wgt[f] = expf(wgt[f] - mx); sum += wgt[f]; }
    float inv = 1.f / sum;
#pragma unroll
    for (int f = 0; f < F_; f++) wgt[f] *= inv;

#pragma unroll
    for (int f = 0; f < F_; f++)
        if (l == f)
            attn2[(((long)b * H_ + w) * N_ + s) * F_ + f] = wgt[f];

    float o0 = 0.f, o1 = 0.f;
#pragma unroll
    for (int f = 0; f < F_; f++) {
        const float2* vf = reinterpret_cast<const float2*>(
            kv + ((long)m * F_ + f) * (2 * C_) + C_ + w * DH_);
        float2 vv = vf[l];
        o0 += wgt[f] * vv.x;
        o1 += wgt[f] * vv.y;
    }
    out2[(long)m * KPACK + w * 32 + l] = split2(o0, o1);
}

// ---------------- host launcher ----------------------------------------------
template<int EPI>
static void launch_gemm(const uint2* A, const uint2* B, void* C,
                        int M, int N, int K, int ldap, int ldbp, int ldc,
                        int Z, int Z2,
                        long sA1, long sA2, long sB1, long sB2,
                        long sC1, long sC2, float alpha, const float* bias)
{
    dim3 grid((N + 255) / 256, (M + 127) / 128, Z);
    gemm_sp<EPI><<<grid, 256, SMEM_BYTES>>>(A, B, C, M, N, K, ldap, ldbp, ldc,
                                            Z2, sA1, sA2, sB1, sB2, sC1, sC2,
                                            alpha, bias);
}

extern "C" void kernel_launch(void* const* d_in, const int* in_sizes, int n_in,
                              void* d_out, int out_size)
{
    (void)in_sizes; (void)n_in; (void)out_size;
    const float* x      = (const float*)d_in[0];
    const float* W_qkv  = (const float*)d_in[1];
    const float* W_q2   = (const float*)d_in[2];
    const float* W_kv2  = (const float*)d_in[3];
    const float* W_proj = (const float*)d_in[4];
    const float* b_proj = (const float*)d_in[5];
    float* out = (float*)d_out;

    static bool attr_set = false;
    if (!attr_set) {
        cudaFuncSetAttribute(gemm_sp<0>, cudaFuncAttributeMaxDynamicSharedMemorySize, SMEM_BYTES);
        cudaFuncSetAttribute(gemm_sp<1>, cudaFuncAttributeMaxDynamicSharedMemorySize, SMEM_BYTES);
        cudaFuncSetAttribute(gemm_sp<2>, cudaFuncAttributeMaxDynamicSharedMemorySize, SMEM_BYTES);
        attr_set = true;
    }

    uint2 *pxsp, *pqkvsp, *pattn1, *pvt, *pxosp, *pxdsp, *pout2sp;
    uint2 *pwqkvt, *pwq2t, *pwkv2t, *pwprojt;
    float *pscores, *pq2, *pkv;
    cudaGetSymbolAddress((void**)&pxsp,    g_xsp);
    cudaGetSymbolAddress((void**)&pqkvsp,  g_qkvsp);
    cudaGetSymbolAddress((void**)&pscores, g_scores);
    cudaGetSymbolAddress((void**)&pattn1,  g_attn1sp);
    cudaGetSymbolAddress((void**)&pvt,     g_vt);
    cudaGetSymbolAddress((void**)&pxosp,   g_xosp);
    cudaGetSymbolAddress((void**)&pxdsp,   g_xdsp);
    cudaGetSymbolAddress((void**)&pq2,     g_q2);
    cudaGetSymbolAddress((void**)&pkv,     g_k2v2);
    cudaGetSymbolAddress((void**)&pout2sp, g_out2sp);
    cudaGetSymbolAddress((void**)&pwqkvt,  g_wqkvt);
    cudaGetSymbolAddress((void**)&pwq2t,   g_wq2t);
    cudaGetSymbolAddress((void**)&pwkv2t,  g_wkv2t);
    cudaGetSymbolAddress((void**)&pwprojt, g_wprojt);

    const int pb = (int)(((long)M_ * KPACK + 255) / 256);

    // 0) weight transposes + splits
    wsplit<<<(1536 * KPACK + 255) / 256, 256>>>(W_qkv,  pwqkvt, 1536);
    wsplit<<<( 512 * KPACK + 255) / 256, 256>>>(W_q2,   pwq2t,   512);
    wsplit<<<(1024 * KPACK + 255) / 256, 256>>>(W_kv2,  pwkv2t, 1024);
    wsplit<<<( 512 * KPACK + 255) / 256, 256>>>(W_proj, pwprojt, 512);

    // 1) xb -> split packets
    transpose_x_sp<<<pb, 256>>>(x, pxsp);

    // 2) qkv = xb @ W_qkv -> split packets
    launch_gemm<1>(pxsp, pwqkvt, pqkvsp, M_, 3 * C_, C_, KPACK, KPACK, 3 * C_,
                   1, 1, 0, 0, 0, 0, 0, 0, 1.0f, nullptr);

    // 3) scores[b] = scale * Q_b @ K_b^T  (fp32)
    launch_gemm<0>(pqkvsp, pqkvsp + KPACK, pscores, N_, N_, C_,
                   3 * KPACK, 3 * KPACK, N_, B_, 1,
                   (long)N_ * 3 * KPACK, 0, (long)N_ * 3 * KPACK, 0,
                   (long)N_ * N_, 0, 0.125f, nullptr);

    // 4) softmax over P -> attn1 split packets
    softmax_frames_sp<<<M_ * F_, 128>>>(pscores, pattn1);

    // 5) V^T split packets
    vtrans<<<(int)(((long)B_ * F_ * PP_ * C_ + 255) / 256), 256>>>(pqkvsp, pvt);

    // 6) xo[b,:,f,:] = attn1[b,:,f,:] @ V[b,f] -> split packets
    launch_gemm<1>(pattn1, pvt, pxosp, N_, C_, P_,
                   F_ * PP_, PP_, F_ * C_, B_ * F_, F_,
                   (long)N_ * F_ * PP_, (long)PP_,
                   (long)F_ * C_ * PP_, (long)C_ * PP_,
                   (long)N_ * F_ * C_, (long)C_, 1.0f, nullptr);

    // 7) diagonal gather (packets)
    diag_gather_sp<<<pb, 256>>>(pxosp, pxdsp);

    // 8) q2 = (x_diag @ W_q2) * scale  (fp32)
    launch_gemm<0>(pxdsp, pwq2t, pq2, M_, C_, C_, KPACK, KPACK, C_,
                   1, 1, 0, 0, 0, 0, 0, 0, 0.125f, nullptr);

    // 9) k2|v2 = xo @ W_kv2  (fp32)
    launch_gemm<0>(pxosp, pwkv2t, pkv, MKV_, 2 * C_, C_, KPACK, KPACK, 2 * C_,
                   1, 1, 0, 0, 0, 0, 0, 0, 1.0f, nullptr);

    // 10) temporal attention; attn2 straight into d_out tail
    stage2_attn<<<M_, 256>>>(pq2, pkv, pout2sp, out + OUT1_);

    // 11) proj + bias + output permutation fused
    launch_gemm<2>(pout2sp, pwprojt, out, M_, C_, C_, KPACK, KPACK, C_,
                   1, 1, 0, 0, 0, 0, 0, 0, 1.0f, b_proj);
}